// round 2
// baseline (speedup 1.0000x reference)
#include <cuda_runtime.h>

#define NN 50000
#define NE 800000
#define NG 128
#define HH 70
#define IND 32

// ---------------- scratch (device globals; no runtime allocation) ----------
__device__ float d_h[NN*HH];
__device__ float d_hnew[NN*HH];
__device__ float d_Ah[NN*HH];
__device__ float d_Bh[NN*HH];
__device__ float d_Dh[NN*HH];
__device__ float d_Eh2[NN*HH];
__device__ float d_e[NE*HH];        // 224 MB
__device__ float d_enew[NE*HH];     // 224 MB
__device__ int   d_cnt[NN];
__device__ int   d_cnt2[NN];
__device__ int   d_ptr[NN+1];
__device__ int   d_eidx[NE];
__device__ float d_part[25000*140]; // per-block bn partials (sum, sumsq)
__device__ float d_sums[140];
__device__ float d_scale[HH];
__device__ float d_shift[HH];
__device__ int   d_gstart[NG+1];

// ---------------- CSR build (deterministic) --------------------------------
__global__ void k_zero_cnt(){
    int i = blockIdx.x*blockDim.x + threadIdx.x;
    if(i < NN){ d_cnt[i]=0; d_cnt2[i]=0; }
}

__global__ void k_hist(const int* __restrict__ dst){
    int i = blockIdx.x*blockDim.x + threadIdx.x;
    if(i < NE) atomicAdd(&d_cnt[dst[i]], 1);
}

__global__ void k_scan(){  // 1 block, 1024 threads: exclusive scan of d_cnt -> d_ptr
    __shared__ int sm[1024];
    __shared__ int carry_s;
    int t = threadIdx.x;
    if(t==0){ d_ptr[0]=0; carry_s=0; }
    __syncthreads();
    for(int base=0; base<NN; base+=1024){
        int v = (base+t < NN) ? d_cnt[base+t] : 0;
        sm[t]=v; __syncthreads();
        for(int off=1; off<1024; off<<=1){
            int x = (t>=off) ? sm[t-off] : 0;
            __syncthreads();
            sm[t]+=x; __syncthreads();
        }
        int incl = sm[t];
        int c = carry_s;
        if(base+t < NN) d_ptr[base+t+1] = c + incl;
        __syncthreads();
        if(t==1023) carry_s = c + incl;
        __syncthreads();
    }
}

__global__ void k_scatter(const int* __restrict__ dst){
    int i = blockIdx.x*blockDim.x + threadIdx.x;
    if(i < NE){
        int d = dst[i];
        int pos = d_ptr[d] + atomicAdd(&d_cnt2[d], 1);
        d_eidx[pos] = i;
    }
}

// canonicalize per-node edge order so float reductions are deterministic
__global__ void k_sortadj(){
    int n = blockIdx.x*blockDim.x + threadIdx.x;
    if(n >= NN) return;
    int lo = d_ptr[n], hi = d_ptr[n+1];
    for(int i=lo+1; i<hi; ++i){
        int v = d_eidx[i];
        int j = i-1;
        while(j>=lo && d_eidx[j] > v){ d_eidx[j+1]=d_eidx[j]; j--; }
        d_eidx[j+1]=v;
    }
}

// ---------------- embeddings ------------------------------------------------
// h0 = nodes_feat @ Wh + bh ; 16 rows/block, 280 threads (c = t%70, rowgroup = t/70)
__global__ void k_emb_h(const float* __restrict__ nf, const float* __restrict__ w,
                        const float* __restrict__ b){
    __shared__ __align__(16) float xs[16*IND];
    __shared__ __align__(16) float Ws[IND*72];
    __shared__ float sb[HH];
    int t = threadIdx.x; int base = blockIdx.x*16;
    for(int idx=t; idx<16*IND; idx+=280) xs[idx] = nf[base*IND + idx];
    for(int idx=t; idx<IND*HH; idx+=280){
        int k = idx/HH, j = idx - k*HH;
        Ws[k*72 + j] = w[idx];
    }
    if(t < HH) sb[t] = b[t];
    __syncthreads();
    int c = t % HH, rg = t / HH;             // rg 0..3, 4 rows each
    float acc[4] = {0.f,0.f,0.f,0.f};
    for(int k4=0; k4<IND; k4+=4){
        float w0 = Ws[(k4+0)*72+c], w1v = Ws[(k4+1)*72+c];
        float w2v = Ws[(k4+2)*72+c], w3v = Ws[(k4+3)*72+c];
        #pragma unroll
        for(int r=0; r<4; r++){
            const float4 xv = *(const float4*)&xs[(rg*4+r)*IND + k4];
            acc[r] = fmaf(xv.x,w0, fmaf(xv.y,w1v, fmaf(xv.z,w2v, fmaf(xv.w,w3v, acc[r]))));
        }
    }
    float bias = sb[c];
    #pragma unroll
    for(int r=0; r<4; r++)
        d_h[(base + rg*4 + r)*HH + c] = acc[r] + bias;
}

// e0[i][j] = ef[i]*we[j] + be[j]
__global__ void k_emb_e(const float* __restrict__ ef, const float* __restrict__ w,
                        const float* __restrict__ b){
    int i = blockIdx.x*blockDim.x + threadIdx.x;
    if(i < NE*HH){
        int row = i / HH, j = i - row*HH;
        d_e[i] = ef[row]*__ldg(&w[j]) + __ldg(&b[j]);
    }
}

// ---------------- per-layer node linear (2 matrices at once) ---------------
// sel=0: write d_Ah,d_Bh ; sel=1: write d_Dh,d_Eh2. 16 rows/block, 280 threads.
__global__ void k_node2(const float* __restrict__ W1, const float* __restrict__ b1,
                        const float* __restrict__ W2, const float* __restrict__ b2,
                        int sel){
    __shared__ __align__(16) float Ws[72*140];
    __shared__ __align__(16) float hs[16*72];
    __shared__ float sb[140];
    int t = threadIdx.x; int base = blockIdx.x*16;
    for(int idx=t; idx<72*140; idx+=280){
        int k = idx/140, cc = idx - k*140;
        float v = 0.f;
        if(k < HH) v = (cc < HH) ? W1[k*HH + cc] : W2[k*HH + (cc-HH)];
        Ws[idx] = v;
    }
    for(int idx=t; idx<16*72; idx+=280){
        int r = idx/72, k = idx - r*72;
        hs[idx] = (k < HH) ? d_h[(base+r)*HH + k] : 0.f;
    }
    if(t < HH){ sb[t]=b1[t]; sb[HH+t]=b2[t]; }
    __syncthreads();
    int c = t % 140, rg = t / 140;           // rg 0..1, 8 rows each
    float acc[8];
    #pragma unroll
    for(int r=0;r<8;r++) acc[r]=0.f;
    for(int k4=0; k4<72; k4+=4){
        float w0 = Ws[(k4+0)*140+c], w1v = Ws[(k4+1)*140+c];
        float w2v = Ws[(k4+2)*140+c], w3v = Ws[(k4+3)*140+c];
        #pragma unroll
        for(int r=0;r<8;r++){
            const float4 hv = *(const float4*)&hs[(rg*8+r)*72 + k4];
            acc[r] = fmaf(hv.x,w0, fmaf(hv.y,w1v, fmaf(hv.z,w2v, fmaf(hv.w,w3v, acc[r]))));
        }
    }
    float bias = sb[c];
    int m = c / HH, j = c - m*HH;
    float* outp = (sel==0) ? ((m==0)?d_Ah:d_Bh) : ((m==0)?d_Dh:d_Eh2);
    #pragma unroll
    for(int r=0;r<8;r++)
        outp[(base + rg*8 + r)*HH + j] = acc[r] + bias;
}

// ---------------- edge kernel: e_new = e@Cw + Cb + Dh[src] + Eh[dst] -------
// also accumulates per-block bn_e partial stats of x = e_new*snorm_e
__global__ void k_edge(const float* __restrict__ Cw, const float* __restrict__ Cb,
                       const int* __restrict__ src, const int* __restrict__ dst,
                       const float* __restrict__ snorm_e){
    __shared__ __align__(16) float Ws[72*72];
    __shared__ __align__(16) float es[32*72];
    __shared__ float sb[HH];
    __shared__ int   ssrc[32], sdst[32];
    __shared__ float ssn[32];
    __shared__ float red[280];
    int t = threadIdx.x; int base = blockIdx.x*32;
    for(int idx=t; idx<72*72; idx+=280){
        int k = idx/72, j = idx - k*72;
        Ws[idx] = (k < HH && j < HH) ? Cw[k*HH + j] : 0.f;
    }
    for(int idx=t; idx<32*72; idx+=280){
        int r = idx/72, k = idx - r*72;
        es[idx] = (k < HH) ? d_e[(base+r)*HH + k] : 0.f;
    }
    if(t < 32){ ssrc[t]=src[base+t]*HH; sdst[t]=dst[base+t]*HH; ssn[t]=snorm_e[base+t]; }
    if(t < HH) sb[t] = Cb[t];
    __syncthreads();
    int c = t % HH, rg = t / HH;             // rg 0..3, 8 rows each
    float acc[8];
    #pragma unroll
    for(int r=0;r<8;r++) acc[r]=0.f;
    for(int k4=0; k4<72; k4+=4){
        float w0 = Ws[(k4+0)*72+c], w1v = Ws[(k4+1)*72+c];
        float w2v = Ws[(k4+2)*72+c], w3v = Ws[(k4+3)*72+c];
        #pragma unroll
        for(int r=0;r<8;r++){
            const float4 ev = *(const float4*)&es[(rg*8+r)*72 + k4];
            acc[r] = fmaf(ev.x,w0, fmaf(ev.y,w1v, fmaf(ev.z,w2v, fmaf(ev.w,w3v, acc[r]))));
        }
    }
    float bias = sb[c];
    float s1=0.f, s2=0.f;
    #pragma unroll
    for(int r=0;r<8;r++){
        int rl = rg*8 + r;
        float v = acc[r] + bias + d_Dh[ssrc[rl]+c] + d_Eh2[sdst[rl]+c];
        d_enew[(base+rl)*HH + c] = v;
        float x = v*ssn[rl];
        s1 += x; s2 = fmaf(x,x,s2);
    }
    red[t]=s1; __syncthreads();
    if(t < HH) d_part[blockIdx.x*140 + t] = red[t] + red[t+70] + red[t+140] + red[t+210];
    __syncthreads();
    red[t]=s2; __syncthreads();
    if(t < HH) d_part[blockIdx.x*140 + 70 + t] = red[t] + red[t+70] + red[t+140] + red[t+210];
}

// ---------------- bn stat reduce + params ----------------------------------
__global__ void k_reduce(int nparts){   // grid 140 blocks, 256 threads; deterministic
    int ch = blockIdx.x, t = threadIdx.x;
    float s = 0.f;
    for(int p=t; p<nparts; p+=256) s += d_part[p*140 + ch];
    __shared__ float sm[256];
    sm[t]=s; __syncthreads();
    for(int off=128; off>0; off>>=1){ if(t<off) sm[t]+=sm[t+off]; __syncthreads(); }
    if(t==0) d_sums[ch]=sm[0];
}

__global__ void k_bnparams(const float* __restrict__ gamma, const float* __restrict__ beta,
                           float invM){
    int c = threadIdx.x;
    if(c < HH){
        float mean = d_sums[c]*invM;
        float var  = d_sums[70+c]*invM - mean*mean;
        float inv  = rsqrtf(var + 1e-5f);
        float sc   = gamma[c]*inv;
        d_scale[c] = sc;
        d_shift[c] = beta[c] - mean*sc;
    }
}

// ---------------- finalizes -------------------------------------------------
__global__ void k_efinal(const float* __restrict__ sn){
    int i = blockIdx.x*blockDim.x + threadIdx.x;
    if(i < NE*HH){
        int row = i / HH, j = i - row*HH;
        float x = d_enew[i]*sn[row];
        float y = d_scale[j]*x + d_shift[j];
        d_e[i] += fmaxf(y, 0.f);
    }
}

__global__ void k_hfinal(){
    int i = blockIdx.x*blockDim.x + threadIdx.x;
    if(i < NN*HH){
        int j = i % HH;
        float y = d_scale[j]*d_hnew[i] + d_shift[j];
        d_h[i] += fmaxf(y, 0.f);
    }
}

// ---------------- aggregation (warp per node, CSR, no atomics) -------------
__global__ void k_agg(const int* __restrict__ src, const float* __restrict__ snorm_n){
    __shared__ float sm1[8*HH];
    int wi = threadIdx.x >> 5;
    int lane = threadIdx.x & 31;
    int n = blockIdx.x*8 + wi;
    int c0=lane, c1=lane+32, c2=lane+64;
    bool has2 = (c2 < HH);
    float num0=0.f,num1=0.f,num2=0.f,den0=0.f,den1=0.f,den2=0.f;
    int s0 = d_ptr[n], s1 = d_ptr[n+1];
    for(int j=s0; j<s1; j++){
        int eid = d_eidx[j];
        int ep = eid*HH;
        int sp = src[eid]*HH;
        float e0 = d_enew[ep+c0], e1 = d_enew[ep+c1];
        float b0 = d_Bh[sp+c0],   b1 = d_Bh[sp+c1];
        float g0 = __fdividef(1.f, 1.f + __expf(-e0));
        float g1 = __fdividef(1.f, 1.f + __expf(-e1));
        num0 = fmaf(g0,b0,num0); den0 += g0;
        num1 = fmaf(g1,b1,num1); den1 += g1;
        if(has2){
            float e2 = d_enew[ep+c2], b2v = d_Bh[sp+c2];
            float g2 = __fdividef(1.f, 1.f + __expf(-e2));
            num2 = fmaf(g2,b2v,num2); den2 += g2;
        }
    }
    float snv = snorm_n[n];
    int base = n*HH;
    float x0 = (d_Ah[base+c0] + __fdividef(num0, den0+1e-6f))*snv;
    float x1v= (d_Ah[base+c1] + __fdividef(num1, den1+1e-6f))*snv;
    d_hnew[base+c0]=x0; d_hnew[base+c1]=x1v;
    sm1[wi*HH+c0]=x0; sm1[wi*HH+c1]=x1v;
    if(has2){
        float x2v = (d_Ah[base+c2] + __fdividef(num2, den2+1e-6f))*snv;
        d_hnew[base+c2]=x2v;
        sm1[wi*HH+c2]=x2v;
    }
    __syncthreads();
    int t = threadIdx.x;
    if(t < HH){
        float p1=0.f, p2=0.f;
        #pragma unroll
        for(int k=0;k<8;k++){ float v=sm1[k*HH+t]; p1+=v; p2=fmaf(v,v,p2); }
        d_part[blockIdx.x*140 + t]      = p1;
        d_part[blockIdx.x*140 + 70 + t] = p2;
    }
}

// ---------------- readout + MLP --------------------------------------------
__global__ void k_gstart(const int* __restrict__ gids){
    int g = threadIdx.x;
    if(g > NG) return;
    if(g == NG){ d_gstart[NG]=NN; return; }
    int lo=0, hi=NN;
    while(lo < hi){
        int mid = (lo+hi)>>1;
        if(gids[mid] < g) lo = mid+1; else hi = mid;
    }
    d_gstart[g] = lo;
}

__global__ void k_readout(const float* __restrict__ w0, const float* __restrict__ b0,
                          const float* __restrict__ w1, const float* __restrict__ b1,
                          const float* __restrict__ w2, const float* __restrict__ b2,
                          float* __restrict__ out){
    int g = blockIdx.x;
    int s = d_gstart[g], e = d_gstart[g+1];
    int cnt = e - s;
    __shared__ float red[210];
    __shared__ float hg[HH];
    __shared__ float x1[35];
    __shared__ float x2[17];
    int t = threadIdx.x;
    if(t < 210){
        int c = t % HH, gr = t / HH;        // 3 strided groups, fixed order
        float ps = 0.f;
        for(int n=s+gr; n<e; n+=3) ps += d_h[n*HH + c];
        red[t] = ps;
    }
    __syncthreads();
    if(t < HH) hg[t] = (red[t] + red[70+t] + red[140+t]) / fmaxf((float)cnt, 1.f);
    __syncthreads();
    if(t < 35){
        float a = b0[t];
        for(int k=0;k<HH;k++) a = fmaf(hg[k], w0[k*35+t], a);
        x1[t] = fmaxf(a, 0.f);
    }
    __syncthreads();
    if(t < 17){
        float a = b1[t];
        for(int k=0;k<35;k++) a = fmaf(x1[k], w1[k*17+t], a);
        x2[t] = fmaxf(a, 0.f);
    }
    __syncthreads();
    if(t < 10){
        float a = b2[t];
        for(int k=0;k<17;k++) a = fmaf(x2[k], w2[k*10+t], a);
        out[g*10 + t] = a;
    }
}

// ---------------- host orchestration ---------------------------------------
extern "C" void kernel_launch(void* const* d_in, const int* in_sizes, int n_in,
                              void* d_out, int out_size){
    const float* nodes_feat = (const float*)d_in[0];
    const float* edges_feat = (const float*)d_in[1];
    const float* snorm_n    = (const float*)d_in[2];
    const float* snorm_e    = (const float*)d_in[3];
    const float* emb_h_w    = (const float*)d_in[4];
    const float* emb_h_b    = (const float*)d_in[5];
    const float* emb_e_w    = (const float*)d_in[6];
    const float* emb_e_b    = (const float*)d_in[7];
    const float* Aw = (const float*)d_in[8];  const float* Ab = (const float*)d_in[9];
    const float* Bw = (const float*)d_in[10]; const float* Bb = (const float*)d_in[11];
    const float* Cw = (const float*)d_in[12]; const float* Cb = (const float*)d_in[13];
    const float* Dw = (const float*)d_in[14]; const float* Db = (const float*)d_in[15];
    const float* Ew = (const float*)d_in[16]; const float* Eb = (const float*)d_in[17];
    const float* bn_h_g = (const float*)d_in[18]; const float* bn_h_b = (const float*)d_in[19];
    const float* bn_e_g = (const float*)d_in[20]; const float* bn_e_b = (const float*)d_in[21];
    const float* w0 = (const float*)d_in[22]; const float* b0 = (const float*)d_in[23];
    const float* w1 = (const float*)d_in[24]; const float* b1 = (const float*)d_in[25];
    const float* w2 = (const float*)d_in[26]; const float* b2 = (const float*)d_in[27];
    const int* src  = (const int*)d_in[28];
    const int* dst  = (const int*)d_in[29];
    const int* gids = (const int*)d_in[30];
    float* out = (float*)d_out;

    // CSR (deterministic: canonical sort per node)
    k_zero_cnt<<<(NN+255)/256, 256>>>();
    k_hist<<<(NE+255)/256, 256>>>(dst);
    k_scan<<<1, 1024>>>();
    k_scatter<<<(NE+255)/256, 256>>>(dst);
    k_sortadj<<<(NN+255)/256, 256>>>();

    // embeddings
    k_emb_h<<<NN/16, 280>>>(nodes_feat, emb_h_w, emb_h_b);
    k_emb_e<<<(NE*HH+255)/256, 256>>>(edges_feat, emb_e_w, emb_e_b);

    for(int l=0; l<4; l++){
        size_t wo = (size_t)l*HH*HH, bo = (size_t)l*HH;
        k_node2<<<NN/16, 280>>>(Aw+wo, Ab+bo, Bw+wo, Bb+bo, 0);
        k_node2<<<NN/16, 280>>>(Dw+wo, Db+bo, Ew+wo, Eb+bo, 1);
        k_edge<<<NE/32, 280>>>(Cw+wo, Cb+bo, src, dst, snorm_e);
        if(l < 3){  // e is dead after the last layer: skip bn_e + finalize
            k_reduce<<<140, 256>>>(NE/32);
            k_bnparams<<<1, 70>>>(bn_e_g+bo, bn_e_b+bo, 1.f/(float)NE);
            k_efinal<<<(NE*HH+255)/256, 256>>>(snorm_e);
        }
        k_agg<<<NN/8, 256>>>(src, snorm_n);
        k_reduce<<<140, 256>>>(NN/8);
        k_bnparams<<<1, 70>>>(bn_h_g+bo, bn_h_b+bo, 1.f/(float)NN);
        k_hfinal<<<(NN*HH+255)/256, 256>>>();
    }

    k_gstart<<<1, 160>>>(gids);
    k_readout<<<NG, 256>>>(w0, b0, w1, b1, w2, b2, out);
}

// round 4
// speedup vs baseline: 1.3739x; 1.3739x over previous
#include <cuda_runtime.h>

#define NN 50000
#define NE 800000
#define NG 128
#define HH 70
#define HP 72
#define IND 32

// ---------------- scratch (device globals; zero-initialized) ----------------
__device__ float d_h[NN*HP];
__device__ float d_hnew[NN*HP];
__device__ float d_Ah[NN*HP];
__device__ float d_Bh[NN*HP];
__device__ float d_Dh[NN*HP];
__device__ float d_Eh2[NN*HP];
__device__ float d_e[NE*HH];        // 224 MB
__device__ float d_enew[NE*HH];     // 224 MB
__device__ int   d_cnt[NN];
__device__ int   d_cnt2[NN];
__device__ int   d_ptr[NN+1];
__device__ int   d_eidx[NE];
__device__ int   d_bs[256];
__device__ int   d_bsx[256];
__device__ float d_part[12500*140];
__device__ float d_part2[64*140];
__device__ float d_sums[140];
__device__ float d_scaleE[HH], d_shiftE[HH];
__device__ float d_scaleH[HH], d_shiftH[HH];
__device__ int   d_gstart[NG+1];

// ---------------- CSR build (deterministic) --------------------------------
__global__ void k_zero_cnt(){
    int i = blockIdx.x*blockDim.x + threadIdx.x;
    if(i < NN){ d_cnt[i]=0; d_cnt2[i]=0; }
}

__global__ void k_hist(const int* __restrict__ dst){
    int i = blockIdx.x*blockDim.x + threadIdx.x;
    if(i < NE) atomicAdd(&d_cnt[dst[i]], 1);
}

// multi-block scan: A) block sums, B) scan block sums, C) per-block scan + add
__global__ void k_scanA(){
    __shared__ int sm[256];
    int t = threadIdx.x, i = blockIdx.x*256 + t;
    sm[t] = (i < NN) ? d_cnt[i] : 0;
    __syncthreads();
    for(int off=128; off>0; off>>=1){ if(t<off) sm[t]+=sm[t+off]; __syncthreads(); }
    if(t==0) d_bs[blockIdx.x] = sm[0];
}
__global__ void k_scanB(int nb){
    __shared__ int sm[256];
    int t = threadIdx.x;
    int v = (t < nb) ? d_bs[t] : 0;
    sm[t] = v; __syncthreads();
    for(int off=1; off<256; off<<=1){
        int x = (t>=off) ? sm[t-off] : 0;
        __syncthreads(); sm[t] += x; __syncthreads();
    }
    d_bsx[t] = sm[t] - v;   // exclusive
}
__global__ void k_scanC(){
    __shared__ int sm[256];
    int t = threadIdx.x, b = blockIdx.x, i = b*256 + t;
    int v = (i < NN) ? d_cnt[i] : 0;
    sm[t] = v; __syncthreads();
    for(int off=1; off<256; off<<=1){
        int x = (t>=off) ? sm[t-off] : 0;
        __syncthreads(); sm[t] += x; __syncthreads();
    }
    if(i < NN) d_ptr[i+1] = d_bsx[b] + sm[t];
    if(i == 0) d_ptr[0] = 0;
}

__global__ void k_scatter(const int* __restrict__ dst){
    int i = blockIdx.x*blockDim.x + threadIdx.x;
    if(i < NE){
        int d = dst[i];
        int pos = d_ptr[d] + atomicAdd(&d_cnt2[d], 1);
        d_eidx[pos] = i;
    }
}

__global__ void k_sortadj(){
    int n = blockIdx.x*blockDim.x + threadIdx.x;
    if(n >= NN) return;
    int lo = d_ptr[n], hi = d_ptr[n+1];
    for(int i=lo+1; i<hi; ++i){
        int v = d_eidx[i];
        int j = i-1;
        while(j>=lo && d_eidx[j] > v){ d_eidx[j+1]=d_eidx[j]; j--; }
        d_eidx[j+1]=v;
    }
}

// ---------------- embeddings ------------------------------------------------
__global__ void k_emb_h(const float* __restrict__ nf, const float* __restrict__ w,
                        const float* __restrict__ b){
    __shared__ __align__(16) float xs[16*IND];
    __shared__ __align__(16) float Ws[IND*HP];
    __shared__ float sb[HH];
    int t = threadIdx.x; int base = blockIdx.x*16;
    for(int idx=t; idx<16*IND; idx+=280) xs[idx] = nf[base*IND + idx];
    for(int idx=t; idx<IND*HH; idx+=280){
        int k = idx/HH, j = idx - k*HH;
        Ws[k*HP + j] = w[idx];
    }
    if(t < HH) sb[t] = b[t];
    __syncthreads();
    int c = t % HH, rg = t / HH;
    float acc[4] = {0.f,0.f,0.f,0.f};
    for(int k4=0; k4<IND; k4+=4){
        float w0 = Ws[(k4+0)*HP+c], w1v = Ws[(k4+1)*HP+c];
        float w2v = Ws[(k4+2)*HP+c], w3v = Ws[(k4+3)*HP+c];
        #pragma unroll
        for(int r=0; r<4; r++){
            const float4 xv = *(const float4*)&xs[(rg*4+r)*IND + k4];
            acc[r] = fmaf(xv.x,w0, fmaf(xv.y,w1v, fmaf(xv.z,w2v, fmaf(xv.w,w3v, acc[r]))));
        }
    }
    float bias = sb[c];
    #pragma unroll
    for(int r=0; r<4; r++)
        d_h[(base + rg*4 + r)*HP + c] = acc[r] + bias;
    if(t < 32){  // zero pad cols 70,71
        int r = t >> 1, p = t & 1;
        d_h[(base + r)*HP + HH + p] = 0.f;
    }
}

// e0[i][j] = ef[i]*we[j] + be[j]  (float2)
__global__ void k_emb_e(const float* __restrict__ ef, const float* __restrict__ w,
                        const float* __restrict__ b){
    int i = blockIdx.x*blockDim.x + threadIdx.x;
    if(i < NE*35){
        int row = i / 35, j2 = i - row*35;
        float f = ef[row];
        float2 wv = *(const float2*)&w[j2*2];
        float2 bv = *(const float2*)&b[j2*2];
        float2 o; o.x = fmaf(f, wv.x, bv.x); o.y = fmaf(f, wv.y, bv.y);
        *(float2*)&d_e[row*HH + j2*2] = o;
    }
}

// ---------------- per-layer node linear (2 mats, 8x4 reg tile) --------------
// 32 rows/block, 140 threads: cq = t%35 (4 cols), rg = t/35 (8 rows).
__global__ void __launch_bounds__(140) k_node2(
        const float* __restrict__ W1, const float* __restrict__ b1,
        const float* __restrict__ W2, const float* __restrict__ b2, int sel){
    __shared__ __align__(16) float Ws[HH*140];   // [k][c] 39200B
    __shared__ __align__(16) float hs[32*HP];    // 9216B
    int t = threadIdx.x; int base = blockIdx.x*32;
    for(int idx=t; idx<HH*140; idx+=140){
        int k = idx/140, c = idx - k*140;
        Ws[idx] = (c < HH) ? W1[k*HH + c] : W2[k*HH + (c-HH)];
    }
    for(int idx=t; idx<32*18; idx+=140){
        int r = idx/18, kq = idx - r*18;
        float4 v = make_float4(0.f,0.f,0.f,0.f);
        if(base + r < NN) v = *(const float4*)&d_h[(base+r)*HP + kq*4];
        *(float4*)&hs[r*HP + kq*4] = v;
    }
    __syncthreads();
    int cq = t % 35, rg = t / 35;
    int c0 = cq*4;
    float acc[8][4];
    #pragma unroll
    for(int r=0;r<8;r++){ acc[r][0]=0.f; acc[r][1]=0.f; acc[r][2]=0.f; acc[r][3]=0.f; }
    #pragma unroll 2
    for(int k=0; k<68; k+=4){
        float4 wa = *(const float4*)&Ws[(k+0)*140 + c0];
        float4 wb = *(const float4*)&Ws[(k+1)*140 + c0];
        float4 wc = *(const float4*)&Ws[(k+2)*140 + c0];
        float4 wd = *(const float4*)&Ws[(k+3)*140 + c0];
        #pragma unroll
        for(int r=0;r<8;r++){
            float4 hv = *(const float4*)&hs[(rg*8+r)*HP + k];
            acc[r][0] = fmaf(hv.x,wa.x, fmaf(hv.y,wb.x, fmaf(hv.z,wc.x, fmaf(hv.w,wd.x, acc[r][0]))));
            acc[r][1] = fmaf(hv.x,wa.y, fmaf(hv.y,wb.y, fmaf(hv.z,wc.y, fmaf(hv.w,wd.y, acc[r][1]))));
            acc[r][2] = fmaf(hv.x,wa.z, fmaf(hv.y,wb.z, fmaf(hv.z,wc.z, fmaf(hv.w,wd.z, acc[r][2]))));
            acc[r][3] = fmaf(hv.x,wa.w, fmaf(hv.y,wb.w, fmaf(hv.z,wc.w, fmaf(hv.w,wd.w, acc[r][3]))));
        }
    }
    {   // k = 68,69 tail
        float4 wa = *(const float4*)&Ws[68*140 + c0];
        float4 wb = *(const float4*)&Ws[69*140 + c0];
        #pragma unroll
        for(int r=0;r<8;r++){
            float2 hv = *(const float2*)&hs[(rg*8+r)*HP + 68];
            acc[r][0] = fmaf(hv.x,wa.x, fmaf(hv.y,wb.x, acc[r][0]));
            acc[r][1] = fmaf(hv.x,wa.y, fmaf(hv.y,wb.y, acc[r][1]));
            acc[r][2] = fmaf(hv.x,wa.z, fmaf(hv.y,wb.z, acc[r][2]));
            acc[r][3] = fmaf(hv.x,wa.w, fmaf(hv.y,wb.w, acc[r][3]));
        }
    }
    #pragma unroll
    for(int cc=0; cc<4; cc++){
        int c = c0 + cc;
        int m = (c >= HH) ? 1 : 0;
        int j = c - HH*m;
        const float* bb = m ? b2 : b1;
        float* outp = sel ? (m ? d_Eh2 : d_Dh) : (m ? d_Bh : d_Ah);
        float bias = __ldg(&bb[j]);
        #pragma unroll
        for(int r=0;r<8;r++){
            int row = base + rg*8 + r;
            if(row < NN) outp[row*HP + j] = acc[r][cc] + bias;
        }
    }
}

// ---------------- edge kernel (fused residual-in, 8x4 reg tile) -------------
// 64 edges/block, 144 threads: cq = t%18 (4 cols), rg = t/18 (8 rows).
// fuse=0: es = d_e.  fuse=1: es = d_e + relu(bn_e(d_enew*snorm)); if write_e, store to d_e.
// writes d_enew, and bn_e partial stats of enew*snorm.
__global__ void __launch_bounds__(144) k_edge(
        const float* __restrict__ Cw, const float* __restrict__ Cb,
        const int* __restrict__ src, const int* __restrict__ dst,
        const float* __restrict__ snorm_e, int fuse, int write_e){
    __shared__ __align__(16) float Ws[HP*HP];    // 20736B
    __shared__ __align__(16) float es[64*HP];    // 18432B
    __shared__ float sb[HP];
    __shared__ int   ssrc[64], sdst[64];
    __shared__ float ssn[64];
    __shared__ float sE[HH], sH[HH];
    int t = threadIdx.x; int base = blockIdx.x*64;

    for(int idx=t; idx<HP*HP; idx+=144){
        int k = idx/HP, j = idx - k*HP;
        Ws[idx] = (k < HH && j < HH) ? Cw[k*HH + j] : 0.f;
    }
    if(t < 64){
        int ei = base + t;
        ssrc[t] = src[ei]*HP; sdst[t] = dst[ei]*HP; ssn[t] = snorm_e[ei];
    }
    if(t < HP) sb[t] = (t < HH) ? Cb[t] : 0.f;
    if(fuse && t < HH){ sE[t] = d_scaleE[t]; sH[t] = d_shiftE[t]; }
    __syncthreads();

    // stage e input (and fused residual update)
    for(int idx=t; idx<64*36; idx+=144){
        int r = idx/36, j2 = idx - r*36;
        if(j2 < 35){
            int g = (base+r)*HH + j2*2;
            float2 val;
            if(fuse){
                float2 en = *(const float2*)&d_enew[g];
                float2 ep = *(const float2*)&d_e[g];
                float snr = ssn[r];
                int j = j2*2;
                float y0 = fmaf(sE[j],   en.x*snr, sH[j]);
                float y1 = fmaf(sE[j+1], en.y*snr, sH[j+1]);
                val.x = ep.x + fmaxf(y0, 0.f);
                val.y = ep.y + fmaxf(y1, 0.f);
                if(write_e) *(float2*)&d_e[g] = val;
            } else {
                val = *(const float2*)&d_e[g];
            }
            *(float2*)&es[r*HP + j2*2] = val;
        } else {
            es[r*HP + 70] = 0.f; es[r*HP + 71] = 0.f;
        }
    }
    __syncthreads();

    int cq = t % 18, rg = t / 18;
    int c0 = cq*4;
    float acc[8][4];
    #pragma unroll
    for(int r=0;r<8;r++){ acc[r][0]=0.f; acc[r][1]=0.f; acc[r][2]=0.f; acc[r][3]=0.f; }
    #pragma unroll 2
    for(int k=0; k<HP; k+=4){
        float4 wa = *(const float4*)&Ws[(k+0)*HP + c0];
        float4 wb = *(const float4*)&Ws[(k+1)*HP + c0];
        float4 wc = *(const float4*)&Ws[(k+2)*HP + c0];
        float4 wd = *(const float4*)&Ws[(k+3)*HP + c0];
        #pragma unroll
        for(int r=0;r<8;r++){
            float4 ev = *(const float4*)&es[(rg*8+r)*HP + k];
            acc[r][0] = fmaf(ev.x,wa.x, fmaf(ev.y,wb.x, fmaf(ev.z,wc.x, fmaf(ev.w,wd.x, acc[r][0]))));
            acc[r][1] = fmaf(ev.x,wa.y, fmaf(ev.y,wb.y, fmaf(ev.z,wc.y, fmaf(ev.w,wd.y, acc[r][1]))));
            acc[r][2] = fmaf(ev.x,wa.z, fmaf(ev.y,wb.z, fmaf(ev.z,wc.z, fmaf(ev.w,wd.z, acc[r][2]))));
            acc[r][3] = fmaf(ev.x,wa.w, fmaf(ev.y,wb.w, fmaf(ev.z,wc.w, fmaf(ev.w,wd.w, acc[r][3]))));
        }
    }

    float4 sbv = *(const float4*)&sb[c0];
    bool full = (c0 < 68);
    float s1a[4] = {0.f,0.f,0.f,0.f}, s2a[4] = {0.f,0.f,0.f,0.f};
    #pragma unroll
    for(int r=0;r<8;r++){
        int row = rg*8 + r;
        const float4 dv  = *(const float4*)&d_Dh[ssrc[row] + c0];
        const float4 evv = *(const float4*)&d_Eh2[sdst[row] + c0];
        float v0 = acc[r][0] + sbv.x + dv.x + evv.x;
        float v1 = acc[r][1] + sbv.y + dv.y + evv.y;
        float v2 = acc[r][2] + sbv.z + dv.z + evv.z;
        float v3 = acc[r][3] + sbv.w + dv.w + evv.w;
        int g = (base+row)*HH + c0;
        *(float2*)&d_enew[g] = make_float2(v0, v1);
        if(full) *(float2*)&d_enew[g+2] = make_float2(v2, v3);
        float snr = ssn[row];
        float x0 = v0*snr, x1 = v1*snr;
        float x2 = full ? v2*snr : 0.f;
        float x3 = full ? v3*snr : 0.f;
        s1a[0]+=x0; s2a[0]=fmaf(x0,x0,s2a[0]);
        s1a[1]+=x1; s2a[1]=fmaf(x1,x1,s2a[1]);
        s1a[2]+=x2; s2a[2]=fmaf(x2,x2,s2a[2]);
        s1a[3]+=x3; s2a[3]=fmaf(x3,x3,s2a[3]);
    }
    __syncthreads();
    float* sred = es;   // reuse
    #pragma unroll
    for(int cc=0;cc<4;cc++){
        sred[rg*144 + c0 + cc]      = s1a[cc];
        sred[rg*144 + 72 + c0 + cc] = s2a[cc];
    }
    __syncthreads();
    if(t < 140){
        int slot = (t < HH) ? t : (t - HH + HP);
        float p = 0.f;
        #pragma unroll
        for(int g=0; g<8; g++) p += sred[g*144 + slot];
        d_part[blockIdx.x*140 + t] = p;
    }
}

// ---------------- bn stat reduce + params ----------------------------------
__global__ void k_red1(int nparts, int chunk){
    int b = blockIdx.x, t = threadIdx.x;
    if(t >= 140) return;
    int lo = b*chunk, hi = min(lo + chunk, nparts);
    float s = 0.f;
    for(int p=lo; p<hi; p++) s += d_part[p*140 + t];
    d_part2[b*140 + t] = s;
}
__global__ void k_red2(){
    int t = threadIdx.x;
    if(t >= 140) return;
    float s = 0.f;
    #pragma unroll 4
    for(int b=0; b<64; b++) s += d_part2[b*140 + t];
    d_sums[t] = s;
}

__global__ void k_bnparams(const float* __restrict__ gamma, const float* __restrict__ beta,
                           float invM, int selE){
    int c = threadIdx.x;
    if(c < HH){
        float mean = d_sums[c]*invM;
        float var  = d_sums[70+c]*invM - mean*mean;
        float inv  = rsqrtf(var + 1e-5f);
        float sc   = gamma[c]*inv;
        float sh   = beta[c] - mean*sc;
        if(selE){ d_scaleE[c]=sc; d_shiftE[c]=sh; }
        else    { d_scaleH[c]=sc; d_shiftH[c]=sh; }
    }
}

// ---------------- h finalize -------------------------------------------------
__global__ void k_hfinal(){
    int i2 = blockIdx.x*blockDim.x + threadIdx.x;
    if(i2 >= NN*36) return;
    int row = i2/36, j2 = i2 - row*36;
    if(j2 < 35){
        int j = j2*2, g = row*HP + j;
        float2 v = *(const float2*)&d_hnew[g];
        float y0 = fmaf(__ldg(&d_scaleH[j]),   v.x, __ldg(&d_shiftH[j]));
        float y1 = fmaf(__ldg(&d_scaleH[j+1]), v.y, __ldg(&d_shiftH[j+1]));
        float2 h = *(const float2*)&d_h[g];
        h.x += fmaxf(y0, 0.f); h.y += fmaxf(y1, 0.f);
        *(float2*)&d_h[g] = h;
    }
}

// ---------------- aggregation (warp per node, CSR, no atomics) -------------
__global__ void k_agg(const int* __restrict__ src, const float* __restrict__ snorm_n){
    __shared__ float sm1[8*HH];
    int wi = threadIdx.x >> 5;
    int lane = threadIdx.x & 31;
    int n = blockIdx.x*8 + wi;
    int c0=lane, c1=lane+32, c2=lane+64;
    bool has2 = (c2 < HH);
    float num0=0.f,num1=0.f,num2=0.f,den0=0.f,den1=0.f,den2=0.f;
    int s0 = d_ptr[n], s1 = d_ptr[n+1];
    for(int j=s0; j<s1; j++){
        int eid = d_eidx[j];
        int ep = eid*HH;
        int sp = src[eid]*HP;
        float e0 = d_enew[ep+c0], e1 = d_enew[ep+c1];
        float b0 = d_Bh[sp+c0],   b1 = d_Bh[sp+c1];
        float g0 = __fdividef(1.f, 1.f + __expf(-e0));
        float g1 = __fdividef(1.f, 1.f + __expf(-e1));
        num0 = fmaf(g0,b0,num0); den0 += g0;
        num1 = fmaf(g1,b1,num1); den1 += g1;
        if(has2){
            float e2 = d_enew[ep+c2], b2v = d_Bh[sp+c2];
            float g2 = __fdividef(1.f, 1.f + __expf(-e2));
            num2 = fmaf(g2,b2v,num2); den2 += g2;
        }
    }
    float snv = snorm_n[n];
    int base = n*HP;
    float x0 = (d_Ah[base+c0] + __fdividef(num0, den0+1e-6f))*snv;
    float x1v= (d_Ah[base+c1] + __fdividef(num1, den1+1e-6f))*snv;
    d_hnew[base+c0]=x0; d_hnew[base+c1]=x1v;
    sm1[wi*HH+c0]=x0; sm1[wi*HH+c1]=x1v;
    if(has2){
        float x2v = (d_Ah[base+c2] + __fdividef(num2, den2+1e-6f))*snv;
        d_hnew[base+c2]=x2v;
        sm1[wi*HH+c2]=x2v;
    }
    __syncthreads();
    int t = threadIdx.x;
    if(t < HH){
        float p1=0.f, p2=0.f;
        #pragma unroll
        for(int k=0;k<8;k++){ float v=sm1[k*HH+t]; p1+=v; p2=fmaf(v,v,p2); }
        d_part[blockIdx.x*140 + t]      = p1;
        d_part[blockIdx.x*140 + 70 + t] = p2;
    }
}

// ---------------- readout + MLP --------------------------------------------
__global__ void k_gstart(const int* __restrict__ gids){
    int g = threadIdx.x;
    if(g > NG) return;
    if(g == NG){ d_gstart[NG]=NN; return; }
    int lo=0, hi=NN;
    while(lo < hi){
        int mid = (lo+hi)>>1;
        if(gids[mid] < g) lo = mid+1; else hi = mid;
    }
    d_gstart[g] = lo;
}

__global__ void k_readout(const float* __restrict__ w0, const float* __restrict__ b0,
                          const float* __restrict__ w1, const float* __restrict__ b1,
                          const float* __restrict__ w2, const float* __restrict__ b2,
                          float* __restrict__ out){
    int g = blockIdx.x;
    int s = d_gstart[g], e = d_gstart[g+1];
    int cnt = e - s;
    __shared__ float red[210];
    __shared__ float hg[HH];
    __shared__ float x1[35];
    __shared__ float x2[17];
    int t = threadIdx.x;
    if(t < 210){
        int c = t % HH, gr = t / HH;
        float ps = 0.f;
        for(int n=s+gr; n<e; n+=3) ps += d_h[n*HP + c];
        red[t] = ps;
    }
    __syncthreads();
    if(t < HH) hg[t] = (red[t] + red[70+t] + red[140+t]) / fmaxf((float)cnt, 1.f);
    __syncthreads();
    if(t < 35){
        float a = b0[t];
        for(int k=0;k<HH;k++) a = fmaf(hg[k], w0[k*35+t], a);
        x1[t] = fmaxf(a, 0.f);
    }
    __syncthreads();
    if(t < 17){
        float a = b1[t];
        for(int k=0;k<35;k++) a = fmaf(x1[k], w1[k*17+t], a);
        x2[t] = fmaxf(a, 0.f);
    }
    __syncthreads();
    if(t < 10){
        float a = b2[t];
        for(int k=0;k<17;k++) a = fmaf(x2[k], w2[k*10+t], a);
        out[g*10 + t] = a;
    }
}

// ---------------- host orchestration ---------------------------------------
extern "C" void kernel_launch(void* const* d_in, const int* in_sizes, int n_in,
                              void* d_out, int out_size){
    const float* nodes_feat = (const float*)d_in[0];
    const float* edges_feat = (const float*)d_in[1];
    const float* snorm_n    = (const float*)d_in[2];
    const float* snorm_e    = (const float*)d_in[3];
    const float* emb_h_w    = (const float*)d_in[4];
    const float* emb_h_b    = (const float*)d_in[5];
    const float* emb_e_w    = (const float*)d_in[6];
    const float* emb_e_b    = (const float*)d_in[7];
    const float* Aw = (const float*)d_in[8];  const float* Ab = (const float*)d_in[9];
    const float* Bw = (const float*)d_in[10]; const float* Bb = (const float*)d_in[11];
    const float* Cw = (const float*)d_in[12]; const float* Cb = (const float*)d_in[13];
    const float* Dw = (const float*)d_in[14]; const float* Db = (const float*)d_in[15];
    const float* Ew = (const float*)d_in[16]; const float* Eb = (const float*)d_in[17];
    const float* bn_h_g = (const float*)d_in[18]; const float* bn_h_b = (const float*)d_in[19];
    const float* bn_e_g = (const float*)d_in[20]; const float* bn_e_b = (const float*)d_in[21];
    const float* w0 = (const float*)d_in[22]; const float* b0 = (const float*)d_in[23];
    const float* w1 = (const float*)d_in[24]; const float* b1 = (const float*)d_in[25];
    const float* w2 = (const float*)d_in[26]; const float* b2 = (const float*)d_in[27];
    const int* src  = (const int*)d_in[28];
    const int* dst  = (const int*)d_in[29];
    const int* gids = (const int*)d_in[30];
    float* out = (float*)d_out;

    // CSR (deterministic)
    k_zero_cnt<<<(NN+255)/256, 256>>>();
    k_hist<<<(NE+255)/256, 256>>>(dst);
    int nb = (NN+255)/256;               // 196
    k_scanA<<<nb, 256>>>();
    k_scanB<<<1, 256>>>(nb);
    k_scanC<<<nb, 256>>>();
    k_scatter<<<(NE+255)/256, 256>>>(dst);
    k_sortadj<<<(NN+255)/256, 256>>>();

    // embeddings
    k_emb_h<<<NN/16, 280>>>(nodes_feat, emb_h_w, emb_h_b);
    k_emb_e<<<(NE*35+255)/256, 256>>>(edges_feat, emb_e_w, emb_e_b);

    const int EPARTS = NE/64;            // 12500
    const int HPARTS = NN/8;             // 6250
    for(int l=0; l<4; l++){
        size_t wo = (size_t)l*HH*HH, bo = (size_t)l*HH;
        k_node2<<<(NN+31)/32, 140>>>(Aw+wo, Ab+bo, Bw+wo, Bb+bo, 0);
        k_node2<<<(NN+31)/32, 140>>>(Dw+wo, Db+bo, Ew+wo, Eb+bo, 1);
        int fuse = (l > 0), we = (l > 0 && l < 3);
        k_edge<<<NE/64, 144>>>(Cw+wo, Cb+bo, src, dst, snorm_e, fuse, we);
        if(l < 3){
            k_red1<<<64, 160>>>(EPARTS, (EPARTS+63)/64);
            k_red2<<<1, 160>>>();
            k_bnparams<<<1, 70>>>(bn_e_g+bo, bn_e_b+bo, 1.f/(float)NE, 1);
        }
        k_agg<<<NN/8, 256>>>(src, snorm_n);
        k_red1<<<64, 160>>>(HPARTS, (HPARTS+63)/64);
        k_red2<<<1, 160>>>();
        k_bnparams<<<1, 70>>>(bn_h_g+bo, bn_h_b+bo, 1.f/(float)NN, 0);
        k_hfinal<<<(NN*36+255)/256, 256>>>();
    }

    k_gstart<<<1, 160>>>(gids);
    k_readout<<<NG, 256>>>(w0, b0, w1, b1, w2, b2, out);
}

// round 5
// speedup vs baseline: 1.7941x; 1.3058x over previous
#include <cuda_runtime.h>

#define NN 50000
#define NE 800000
#define NG 128
#define HH 70
#define HP 72
#define IND 32

// ---------------- scratch (device globals; zero-initialized) ----------------
__device__ float d_h[NN*HP];
__device__ float d_hnew[NN*HP];
__device__ float d_Ah[NN*HP];
__device__ float d_Bh[NN*HP];
__device__ float d_Dh[NN*HP];
__device__ float d_Eh2[NN*HP];
__device__ float d_e[NE*HH];        // 224 MB
__device__ float d_enew[NE*HH];     // 224 MB
__device__ int   d_cnt[NN];
__device__ int   d_cnt2[NN];
__device__ int   d_ptr[NN+1];
__device__ int   d_eidx[NE];
__device__ int   d_esrc[NE];
__device__ int   d_bs[256];
__device__ int   d_bsx[256];
__device__ float d_part[12500*140];
__device__ float d_part2[64*140];
__device__ float d_sums[140];
__device__ float d_scaleE[HH], d_shiftE[HH];
__device__ float d_scaleH[HH], d_shiftH[HH];
__device__ float d_weC[HP], d_beC[HP];
__device__ int   d_gstart[NG+1];

// ---------------- packed-fp32 helpers ---------------------------------------
__device__ __forceinline__ unsigned long long bc2(float w){
    unsigned long long r;
    asm("mov.b64 %0, {%1, %1};" : "=l"(r) : "f"(w));
    return r;
}
__device__ __forceinline__ void fma2(float2 &c, float2 a, unsigned long long bw){
    unsigned long long ca = *(unsigned long long*)&a;
    unsigned long long cc = *(unsigned long long*)&c;
    asm("fma.rn.f32x2 %0, %1, %2, %0;" : "+l"(cc) : "l"(ca), "l"(bw));
    c = *(float2*)&cc;
}
__device__ __forceinline__ float sigm(float x){
    float t;
    asm("tanh.approx.f32 %0, %1;" : "=f"(t) : "f"(x*0.5f));
    return fmaf(t, 0.5f, 0.5f);
}

// ---------------- CSR build (deterministic) --------------------------------
__global__ void k_zero_cnt(){
    int i = blockIdx.x*blockDim.x + threadIdx.x;
    if(i < NN){ d_cnt[i]=0; d_cnt2[i]=0; }
}

__global__ void k_hist(const int* __restrict__ dst){
    int i = blockIdx.x*blockDim.x + threadIdx.x;
    if(i < NE) atomicAdd(&d_cnt[dst[i]], 1);
}

__global__ void k_scanA(){
    __shared__ int sm[256];
    int t = threadIdx.x, i = blockIdx.x*256 + t;
    sm[t] = (i < NN) ? d_cnt[i] : 0;
    __syncthreads();
    for(int off=128; off>0; off>>=1){ if(t<off) sm[t]+=sm[t+off]; __syncthreads(); }
    if(t==0) d_bs[blockIdx.x] = sm[0];
}
__global__ void k_scanB(int nb){
    __shared__ int sm[256];
    int t = threadIdx.x;
    int v = (t < nb) ? d_bs[t] : 0;
    sm[t] = v; __syncthreads();
    for(int off=1; off<256; off<<=1){
        int x = (t>=off) ? sm[t-off] : 0;
        __syncthreads(); sm[t] += x; __syncthreads();
    }
    d_bsx[t] = sm[t] - v;
}
__global__ void k_scanC(){
    __shared__ int sm[256];
    int t = threadIdx.x, b = blockIdx.x, i = b*256 + t;
    int v = (i < NN) ? d_cnt[i] : 0;
    sm[t] = v; __syncthreads();
    for(int off=1; off<256; off<<=1){
        int x = (t>=off) ? sm[t-off] : 0;
        __syncthreads(); sm[t] += x; __syncthreads();
    }
    if(i < NN) d_ptr[i+1] = d_bsx[b] + sm[t];
    if(i == 0) d_ptr[0] = 0;
}

__global__ void k_scatter(const int* __restrict__ dst){
    int i = blockIdx.x*blockDim.x + threadIdx.x;
    if(i < NE){
        int d = dst[i];
        int pos = d_ptr[d] + atomicAdd(&d_cnt2[d], 1);
        d_eidx[pos] = i;
    }
}

__global__ void k_sortadj(const int* __restrict__ src){
    int n = blockIdx.x*blockDim.x + threadIdx.x;
    if(n >= NN) return;
    int lo = d_ptr[n], hi = d_ptr[n+1];
    for(int i=lo+1; i<hi; ++i){
        int v = d_eidx[i];
        int j = i-1;
        while(j>=lo && d_eidx[j] > v){ d_eidx[j+1]=d_eidx[j]; j--; }
        d_eidx[j+1]=v;
    }
    for(int i=lo; i<hi; ++i) d_esrc[i] = src[d_eidx[i]];
}

// ---------------- embeddings / rank-1 precompute ----------------------------
__global__ void k_emb_h(const float* __restrict__ nf, const float* __restrict__ w,
                        const float* __restrict__ b){
    __shared__ __align__(16) float xs[16*IND];
    __shared__ __align__(16) float Ws[IND*HP];
    __shared__ float sb[HH];
    int t = threadIdx.x; int base = blockIdx.x*16;
    for(int idx=t; idx<16*IND; idx+=280) xs[idx] = nf[base*IND + idx];
    for(int idx=t; idx<IND*HH; idx+=280){
        int k = idx/HH, j = idx - k*HH;
        Ws[k*HP + j] = w[idx];
    }
    if(t < HH) sb[t] = b[t];
    __syncthreads();
    int c = t % HH, rg = t / HH;
    float acc[4] = {0.f,0.f,0.f,0.f};
    for(int k4=0; k4<IND; k4+=4){
        float w0 = Ws[(k4+0)*HP+c], w1v = Ws[(k4+1)*HP+c];
        float w2v = Ws[(k4+2)*HP+c], w3v = Ws[(k4+3)*HP+c];
        #pragma unroll
        for(int r=0; r<4; r++){
            const float4 xv = *(const float4*)&xs[(rg*4+r)*IND + k4];
            acc[r] = fmaf(xv.x,w0, fmaf(xv.y,w1v, fmaf(xv.z,w2v, fmaf(xv.w,w3v, acc[r]))));
        }
    }
    float bias = sb[c];
    #pragma unroll
    for(int r=0; r<4; r++)
        d_h[(base + rg*4 + r)*HP + c] = acc[r] + bias;
    if(t < 32){
        int r = t >> 1, p = t & 1;
        d_h[(base + r)*HP + HH + p] = 0.f;
    }
}

// weC = we @ Cw0, beC = be @ Cw0 + Cb0  (collapses rank-1 layer-0 edge GEMM)
__global__ void k_wC(const float* __restrict__ we, const float* __restrict__ be,
                     const float* __restrict__ Cw, const float* __restrict__ Cb){
    int j = threadIdx.x;
    if(j >= HP) return;
    if(j < HH){
        float sw = 0.f, sbv = 0.f;
        for(int k=0; k<HH; k++){
            float c = Cw[k*HH + j];
            sw  = fmaf(we[k], c, sw);
            sbv = fmaf(be[k], c, sbv);
        }
        d_weC[j] = sw; d_beC[j] = sbv + Cb[j];
    } else { d_weC[j] = 0.f; d_beC[j] = 0.f; }
}

// ---------------- per-layer node linear (FFMA2, pair-packed rows) -----------
// 32 rows/block, 140 threads: cq=t%35 (4 cols), rg=t/35 (4 row-pairs = 8 rows).
// fuse: stage h = h + relu(bn_h(hnew)) and write back d_h.
__global__ void __launch_bounds__(140) k_node2(
        const float* __restrict__ W1, const float* __restrict__ b1,
        const float* __restrict__ W2, const float* __restrict__ b2,
        int sel, int fuse){
    __shared__ __align__(16) float Ws[HH*140];    // 39200B
    __shared__ __align__(16) float hsp[16*HP*2];  // 9216B pair-interleaved
    __shared__ float sSc[HH], sSh[HH];
    int t = threadIdx.x; int base = blockIdx.x*32;
    for(int idx=t; idx<HH*140; idx+=140){
        int k = idx/140, c = idx - k*140;
        Ws[idx] = (c < HH) ? W1[k*HH + c] : W2[k*HH + (c-HH)];
    }
    if(fuse && t < HH){ sSc[t] = d_scaleH[t]; sSh[t] = d_shiftH[t]; }
    __syncthreads();
    for(int idx=t; idx<32*36; idx+=140){
        int r = idx/36, j2 = idx - r*36;
        int rp = r >> 1, par = r & 1;
        int row = base + r;
        if(j2 < 35){
            int j = j2*2;
            float2 val = make_float2(0.f, 0.f);
            if(row < NN){
                int g = row*HP + j;
                val = *(const float2*)&d_h[g];
                if(fuse){
                    float2 hn = *(const float2*)&d_hnew[g];
                    float y0 = fmaf(sSc[j],   hn.x, sSh[j]);
                    float y1 = fmaf(sSc[j+1], hn.y, sSh[j+1]);
                    val.x += fmaxf(y0, 0.f); val.y += fmaxf(y1, 0.f);
                    *(float2*)&d_h[g] = val;
                }
            }
            hsp[(rp*HP + j)*2 + par]   = val.x;
            hsp[(rp*HP + j+1)*2 + par] = val.y;
        } else {
            hsp[(rp*HP + 70)*2 + par] = 0.f;
            hsp[(rp*HP + 71)*2 + par] = 0.f;
        }
    }
    __syncthreads();
    int cq = t % 35, rg = t / 35;
    int c0 = cq*4;
    float2 acc[4][4];
    #pragma unroll
    for(int rp=0;rp<4;rp++)
        #pragma unroll
        for(int cc=0;cc<4;cc++) acc[rp][cc] = make_float2(0.f,0.f);
    const float* hb = &hsp[(rg*4)*(HP*2)];
    #pragma unroll 5
    for(int k=0; k<HH; k+=2){
        float4 w0 = *(const float4*)&Ws[k*140 + c0];
        float4 w1 = *(const float4*)&Ws[(k+1)*140 + c0];
        unsigned long long b00=bc2(w0.x), b01=bc2(w0.y), b02=bc2(w0.z), b03=bc2(w0.w);
        unsigned long long b10=bc2(w1.x), b11=bc2(w1.y), b12=bc2(w1.z), b13=bc2(w1.w);
        #pragma unroll
        for(int rp=0;rp<4;rp++){
            float4 ev = *(const float4*)&hb[rp*(HP*2) + k*2];
            float2 e0 = make_float2(ev.x, ev.y);
            float2 e1 = make_float2(ev.z, ev.w);
            fma2(acc[rp][0], e0, b00); fma2(acc[rp][0], e1, b10);
            fma2(acc[rp][1], e0, b01); fma2(acc[rp][1], e1, b11);
            fma2(acc[rp][2], e0, b02); fma2(acc[rp][2], e1, b12);
            fma2(acc[rp][3], e0, b03); fma2(acc[rp][3], e1, b13);
        }
    }
    #pragma unroll
    for(int cc=0; cc<4; cc++){
        int c = c0 + cc;
        int m = (c >= HH) ? 1 : 0;
        int j = c - HH*m;
        const float* bb = m ? b2 : b1;
        float* outp = sel ? (m ? d_Eh2 : d_Dh) : (m ? d_Bh : d_Ah);
        float bias = __ldg(&bb[j]);
        #pragma unroll
        for(int rp=0;rp<4;rp++){
            int r0 = base + rg*8 + 2*rp;
            if(r0 < NN)   outp[r0*HP + j]     = acc[rp][cc].x + bias;
            if(r0+1 < NN) outp[(r0+1)*HP + j] = acc[rp][cc].y + bias;
        }
    }
}

// ---------------- edge kernel (FFMA2 pair-packed, fused residual-in) --------
// 64 edges/block, 144 threads: cq=t%18 (4 cols), rg=t/18 (4 row-pairs = 8 rows).
// mode 1: e_prev = rank-1 (ef*we+be); mode 2: e_prev = d_e.
// Always fuse: es = e_prev + relu(bn_e(d_enew*snorm)); write_e -> store to d_e.
__global__ void __launch_bounds__(144) k_edge(
        const float* __restrict__ Cw, const float* __restrict__ Cb,
        const int* __restrict__ src, const int* __restrict__ dst,
        const float* __restrict__ snorm_e,
        const float* __restrict__ ef, const float* __restrict__ we,
        const float* __restrict__ be,
        int mode, int write_e){
    __shared__ __align__(16) float Ws[HP*HP];     // 20736B
    __shared__ __align__(16) float esp[32*HP*2];  // 18432B pair-interleaved
    __shared__ float sb[HP];
    __shared__ int   ssrc[64], sdst[64];
    __shared__ float ssn[64], sef[64];
    __shared__ float sE[HH], sH[HH];
    __shared__ float swe[HP], sbe[HP];
    int t = threadIdx.x; int base = blockIdx.x*64;

    for(int idx=t; idx<HP*HP; idx+=144){
        int k = idx/HP, j = idx - k*HP;
        Ws[idx] = (k < HH && j < HH) ? Cw[k*HH + j] : 0.f;
    }
    if(t < 64){
        int ei = base + t;
        ssrc[t] = src[ei]*HP; sdst[t] = dst[ei]*HP; ssn[t] = snorm_e[ei];
        if(mode == 1) sef[t] = ef[ei];
    }
    if(t < HP) sb[t] = (t < HH) ? Cb[t] : 0.f;
    if(t < HH){ sE[t] = d_scaleE[t]; sH[t] = d_shiftE[t]; }
    if(mode == 1 && t < HP){
        swe[t] = (t < HH) ? we[t] : 0.f;
        sbe[t] = (t < HH) ? be[t] : 0.f;
    }
    __syncthreads();

    for(int idx=t; idx<64*36; idx+=144){
        int r = idx/36, j2 = idx - r*36;
        int rp = r >> 1, par = r & 1;
        if(j2 < 35){
            int j = j2*2;
            int g = (base+r)*HH + j;
            float2 en = *(const float2*)&d_enew[g];
            float2 ep;
            if(mode == 1){
                float fe = sef[r];
                ep.x = fmaf(fe, swe[j],   sbe[j]);
                ep.y = fmaf(fe, swe[j+1], sbe[j+1]);
            } else {
                ep = *(const float2*)&d_e[g];
            }
            float snr = ssn[r];
            float y0 = fmaf(sE[j],   en.x*snr, sH[j]);
            float y1 = fmaf(sE[j+1], en.y*snr, sH[j+1]);
            float2 val;
            val.x = ep.x + fmaxf(y0, 0.f);
            val.y = ep.y + fmaxf(y1, 0.f);
            if(write_e) *(float2*)&d_e[g] = val;
            esp[(rp*HP + j)*2 + par]   = val.x;
            esp[(rp*HP + j+1)*2 + par] = val.y;
        } else {
            esp[(rp*HP + 70)*2 + par] = 0.f;
            esp[(rp*HP + 71)*2 + par] = 0.f;
        }
    }
    __syncthreads();

    int cq = t % 18, rg = t / 18;
    int c0 = cq*4;
    float2 acc[4][4];
    #pragma unroll
    for(int rp=0;rp<4;rp++)
        #pragma unroll
        for(int cc=0;cc<4;cc++) acc[rp][cc] = make_float2(0.f,0.f);
    const float* eb = &esp[(rg*4)*(HP*2)];
    #pragma unroll 6
    for(int k=0; k<HP; k+=2){
        float4 w0 = *(const float4*)&Ws[k*HP + c0];
        float4 w1 = *(const float4*)&Ws[(k+1)*HP + c0];
        unsigned long long b00=bc2(w0.x), b01=bc2(w0.y), b02=bc2(w0.z), b03=bc2(w0.w);
        unsigned long long b10=bc2(w1.x), b11=bc2(w1.y), b12=bc2(w1.z), b13=bc2(w1.w);
        #pragma unroll
        for(int rp=0;rp<4;rp++){
            float4 ev = *(const float4*)&eb[rp*(HP*2) + k*2];
            float2 e0 = make_float2(ev.x, ev.y);
            float2 e1 = make_float2(ev.z, ev.w);
            fma2(acc[rp][0], e0, b00); fma2(acc[rp][0], e1, b10);
            fma2(acc[rp][1], e0, b01); fma2(acc[rp][1], e1, b11);
            fma2(acc[rp][2], e0, b02); fma2(acc[rp][2], e1, b12);
            fma2(acc[rp][3], e0, b03); fma2(acc[rp][3], e1, b13);
        }
    }

    float4 sbv = *(const float4*)&sb[c0];
    bool full = (c0 < 68);
    float s1a[4] = {0.f,0.f,0.f,0.f}, s2a[4] = {0.f,0.f,0.f,0.f};
    #pragma unroll
    for(int rp=0;rp<4;rp++){
        int r0 = rg*8 + 2*rp, r1 = r0+1;
        float4 dv0 = *(const float4*)&d_Dh[ssrc[r0] + c0];
        float4 ev0 = *(const float4*)&d_Eh2[sdst[r0] + c0];
        float4 dv1 = *(const float4*)&d_Dh[ssrc[r1] + c0];
        float4 ev1 = *(const float4*)&d_Eh2[sdst[r1] + c0];
        float v00 = acc[rp][0].x + sbv.x + dv0.x + ev0.x;
        float v01 = acc[rp][1].x + sbv.y + dv0.y + ev0.y;
        float v02 = acc[rp][2].x + sbv.z + dv0.z + ev0.z;
        float v03 = acc[rp][3].x + sbv.w + dv0.w + ev0.w;
        float v10 = acc[rp][0].y + sbv.x + dv1.x + ev1.x;
        float v11 = acc[rp][1].y + sbv.y + dv1.y + ev1.y;
        float v12 = acc[rp][2].y + sbv.z + dv1.z + ev1.z;
        float v13 = acc[rp][3].y + sbv.w + dv1.w + ev1.w;
        int g0 = (base+r0)*HH + c0, g1 = (base+r1)*HH + c0;
        *(float2*)&d_enew[g0] = make_float2(v00, v01);
        *(float2*)&d_enew[g1] = make_float2(v10, v11);
        if(full){
            *(float2*)&d_enew[g0+2] = make_float2(v02, v03);
            *(float2*)&d_enew[g1+2] = make_float2(v12, v13);
        }
        float sn0 = ssn[r0], sn1 = ssn[r1], x;
        x=v00*sn0; s1a[0]+=x; s2a[0]=fmaf(x,x,s2a[0]);
        x=v10*sn1; s1a[0]+=x; s2a[0]=fmaf(x,x,s2a[0]);
        x=v01*sn0; s1a[1]+=x; s2a[1]=fmaf(x,x,s2a[1]);
        x=v11*sn1; s1a[1]+=x; s2a[1]=fmaf(x,x,s2a[1]);
        if(full){
            x=v02*sn0; s1a[2]+=x; s2a[2]=fmaf(x,x,s2a[2]);
            x=v12*sn1; s1a[2]+=x; s2a[2]=fmaf(x,x,s2a[2]);
            x=v03*sn0; s1a[3]+=x; s2a[3]=fmaf(x,x,s2a[3]);
            x=v13*sn1; s1a[3]+=x; s2a[3]=fmaf(x,x,s2a[3]);
        }
    }
    __syncthreads();
    float* sred = esp;
    #pragma unroll
    for(int cc=0;cc<4;cc++){
        sred[rg*144 + c0 + cc]      = s1a[cc];
        sred[rg*144 + 72 + c0 + cc] = s2a[cc];
    }
    __syncthreads();
    if(t < 140){
        int slot = (t < HH) ? t : (t - HH + HP);
        float p = 0.f;
        #pragma unroll
        for(int g=0; g<8; g++) p += sred[g*144 + slot];
        d_part[blockIdx.x*140 + t] = p;
    }
}

// ---------------- layer-0 edge (rank-1, elementwise) ------------------------
__global__ void __launch_bounds__(144) k_edge0(
        const int* __restrict__ src, const int* __restrict__ dst,
        const float* __restrict__ snorm_e, const float* __restrict__ ef){
    __shared__ float sweC[HP], sbeC[HP];
    __shared__ int   ssrc[64], sdst[64];
    __shared__ float ssn[64], sef[64];
    __shared__ float sred[8*144];
    int t = threadIdx.x; int base = blockIdx.x*64;
    if(t < 64){
        int ei = base + t;
        ssrc[t] = src[ei]*HP; sdst[t] = dst[ei]*HP;
        ssn[t] = snorm_e[ei]; sef[t] = ef[ei];
    }
    if(t < HP){ sweC[t] = d_weC[t]; sbeC[t] = d_beC[t]; }
    __syncthreads();
    int cq = t % 18, rg = t / 18;
    int c0 = cq*4;
    float4 wv = *(const float4*)&sweC[c0];
    float4 bv = *(const float4*)&sbeC[c0];
    bool full = (c0 < 68);
    float s1a[4] = {0.f,0.f,0.f,0.f}, s2a[4] = {0.f,0.f,0.f,0.f};
    #pragma unroll
    for(int r=0; r<8; r++){
        int row = rg*8 + r;
        float fe = sef[row];
        float4 dv  = *(const float4*)&d_Dh[ssrc[row] + c0];
        float4 evv = *(const float4*)&d_Eh2[sdst[row] + c0];
        float v0 = fmaf(fe, wv.x, bv.x) + dv.x + evv.x;
        float v1 = fmaf(fe, wv.y, bv.y) + dv.y + evv.y;
        float v2 = fmaf(fe, wv.z, bv.z) + dv.z + evv.z;
        float v3 = fmaf(fe, wv.w, bv.w) + dv.w + evv.w;
        int g = (base+row)*HH + c0;
        *(float2*)&d_enew[g] = make_float2(v0, v1);
        if(full) *(float2*)&d_enew[g+2] = make_float2(v2, v3);
        float snr = ssn[row], x;
        x=v0*snr; s1a[0]+=x; s2a[0]=fmaf(x,x,s2a[0]);
        x=v1*snr; s1a[1]+=x; s2a[1]=fmaf(x,x,s2a[1]);
        if(full){
            x=v2*snr; s1a[2]+=x; s2a[2]=fmaf(x,x,s2a[2]);
            x=v3*snr; s1a[3]+=x; s2a[3]=fmaf(x,x,s2a[3]);
        }
    }
    __syncthreads();
    #pragma unroll
    for(int cc=0;cc<4;cc++){
        sred[rg*144 + c0 + cc]      = s1a[cc];
        sred[rg*144 + 72 + c0 + cc] = s2a[cc];
    }
    __syncthreads();
    if(t < 140){
        int slot = (t < HH) ? t : (t - HH + HP);
        float p = 0.f;
        #pragma unroll
        for(int g=0; g<8; g++) p += sred[g*144 + slot];
        d_part[blockIdx.x*140 + t] = p;
    }
}

// ---------------- bn stat reduce + params ----------------------------------
__global__ void k_red1(int nparts, int chunk){
    int b = blockIdx.x, t = threadIdx.x;
    if(t >= 140) return;
    int lo = b*chunk, hi = min(lo + chunk, nparts);
    float s = 0.f;
    for(int p=lo; p<hi; p++) s += d_part[p*140 + t];
    d_part2[b*140 + t] = s;
}
__global__ void k_red2(){
    int t = threadIdx.x;
    if(t >= 140) return;
    float s = 0.f;
    #pragma unroll 4
    for(int b=0; b<64; b++) s += d_part2[b*140 + t];
    d_sums[t] = s;
}

__global__ void k_bnparams(const float* __restrict__ gamma, const float* __restrict__ beta,
                           float invM, int selE){
    int c = threadIdx.x;
    if(c < HH){
        float mean = d_sums[c]*invM;
        float var  = d_sums[70+c]*invM - mean*mean;
        float inv  = rsqrtf(var + 1e-5f);
        float sc   = gamma[c]*inv;
        float sh   = beta[c] - mean*sc;
        if(selE){ d_scaleE[c]=sc; d_shiftE[c]=sh; }
        else    { d_scaleH[c]=sc; d_shiftH[c]=sh; }
    }
}

// ---------------- h finalize (only after last layer) ------------------------
__global__ void k_hfinal(){
    int i2 = blockIdx.x*blockDim.x + threadIdx.x;
    if(i2 >= NN*36) return;
    int row = i2/36, j2 = i2 - row*36;
    if(j2 < 35){
        int j = j2*2, g = row*HP + j;
        float2 v = *(const float2*)&d_hnew[g];
        float y0 = fmaf(__ldg(&d_scaleH[j]),   v.x, __ldg(&d_shiftH[j]));
        float y1 = fmaf(__ldg(&d_scaleH[j+1]), v.y, __ldg(&d_shiftH[j+1]));
        float2 h = *(const float2*)&d_h[g];
        h.x += fmaxf(y0, 0.f); h.y += fmaxf(y1, 0.f);
        *(float2*)&d_h[g] = h;
    }
}

// ---------------- aggregation (warp per node, CSR, tanh sigmoid) ------------
__global__ void k_agg(const float* __restrict__ snorm_n){
    __shared__ float sm1[8*HH];
    int wi = threadIdx.x >> 5;
    int lane = threadIdx.x & 31;
    int n = blockIdx.x*8 + wi;
    int c0=lane, c1=lane+32, c2=lane+64;
    bool has2 = (c2 < HH);
    float num0=0.f,num1=0.f,num2=0.f,den0=0.f,den1=0.f,den2=0.f;
    int s0 = d_ptr[n], s1 = d_ptr[n+1];
    for(int j=s0; j<s1; j++){
        int eid = d_eidx[j];
        int ep = eid*HH;
        int sp = d_esrc[j]*HP;
        float e0 = d_enew[ep+c0], e1 = d_enew[ep+c1];
        float b0 = d_Bh[sp+c0],   b1 = d_Bh[sp+c1];
        float g0 = sigm(e0);
        float g1 = sigm(e1);
        num0 = fmaf(g0,b0,num0); den0 += g0;
        num1 = fmaf(g1,b1,num1); den1 += g1;
        if(has2){
            float e2 = d_enew[ep+c2], b2v = d_Bh[sp+c2];
            float g2 = sigm(e2);
            num2 = fmaf(g2,b2v,num2); den2 += g2;
        }
    }
    float snv = snorm_n[n];
    int base = n*HP;
    float x0 = (d_Ah[base+c0] + __fdividef(num0, den0+1e-6f))*snv;
    float x1v= (d_Ah[base+c1] + __fdividef(num1, den1+1e-6f))*snv;
    d_hnew[base+c0]=x0; d_hnew[base+c1]=x1v;
    sm1[wi*HH+c0]=x0; sm1[wi*HH+c1]=x1v;
    if(has2){
        float x2v = (d_Ah[base+c2] + __fdividef(num2, den2+1e-6f))*snv;
        d_hnew[base+c2]=x2v;
        sm1[wi*HH+c2]=x2v;
    }
    __syncthreads();
    int t = threadIdx.x;
    if(t < HH){
        float p1=0.f, p2=0.f;
        #pragma unroll
        for(int k=0;k<8;k++){ float v=sm1[k*HH+t]; p1+=v; p2=fmaf(v,v,p2); }
        d_part[blockIdx.x*140 + t]      = p1;
        d_part[blockIdx.x*140 + 70 + t] = p2;
    }
}

// ---------------- readout + MLP --------------------------------------------
__global__ void k_gstart(const int* __restrict__ gids){
    int g = threadIdx.x;
    if(g > NG) return;
    if(g == NG){ d_gstart[NG]=NN; return; }
    int lo=0, hi=NN;
    while(lo < hi){
        int mid = (lo+hi)>>1;
        if(gids[mid] < g) lo = mid+1; else hi = mid;
    }
    d_gstart[g] = lo;
}

__global__ void k_readout(const float* __restrict__ w0, const float* __restrict__ b0,
                          const float* __restrict__ w1, const float* __restrict__ b1,
                          const float* __restrict__ w2, const float* __restrict__ b2,
                          float* __restrict__ out){
    int g = blockIdx.x;
    int s = d_gstart[g], e = d_gstart[g+1];
    int cnt = e - s;
    __shared__ float red[210];
    __shared__ float hg[HH];
    __shared__ float x1[35];
    __shared__ float x2[17];
    int t = threadIdx.x;
    if(t < 210){
        int c = t % HH, gr = t / HH;
        float ps = 0.f;
        for(int n=s+gr; n<e; n+=3) ps += d_h[n*HP + c];
        red[t] = ps;
    }
    __syncthreads();
    if(t < HH) hg[t] = (red[t] + red[70+t] + red[140+t]) / fmaxf((float)cnt, 1.f);
    __syncthreads();
    if(t < 35){
        float a = b0[t];
        for(int k=0;k<HH;k++) a = fmaf(hg[k], w0[k*35+t], a);
        x1[t] = fmaxf(a, 0.f);
    }
    __syncthreads();
    if(t < 17){
        float a = b1[t];
        for(int k=0;k<35;k++) a = fmaf(x1[k], w1[k*17+t], a);
        x2[t] = fmaxf(a, 0.f);
    }
    __syncthreads();
    if(t < 10){
        float a = b2[t];
        for(int k=0;k<17;k++) a = fmaf(x2[k], w2[k*10+t], a);
        out[g*10 + t] = a;
    }
}

// ---------------- host orchestration ---------------------------------------
extern "C" void kernel_launch(void* const* d_in, const int* in_sizes, int n_in,
                              void* d_out, int out_size){
    const float* nodes_feat = (const float*)d_in[0];
    const float* edges_feat = (const float*)d_in[1];
    const float* snorm_n    = (const float*)d_in[2];
    const float* snorm_e    = (const float*)d_in[3];
    const float* emb_h_w    = (const float*)d_in[4];
    const float* emb_h_b    = (const float*)d_in[5];
    const float* emb_e_w    = (const float*)d_in[6];
    const float* emb_e_b    = (const float*)d_in[7];
    const float* Aw = (const float*)d_in[8];  const float* Ab = (const float*)d_in[9];
    const float* Bw = (const float*)d_in[10]; const float* Bb = (const float*)d_in[11];
    const float* Cw = (const float*)d_in[12]; const float* Cb = (const float*)d_in[13];
    const float* Dw = (const float*)d_in[14]; const float* Db = (const float*)d_in[15];
    const float* Ew = (const float*)d_in[16]; const float* Eb = (const float*)d_in[17];
    const float* bn_h_g = (const float*)d_in[18]; const float* bn_h_b = (const float*)d_in[19];
    const float* bn_e_g = (const float*)d_in[20]; const float* bn_e_b = (const float*)d_in[21];
    const float* w0 = (const float*)d_in[22]; const float* b0 = (const float*)d_in[23];
    const float* w1 = (const float*)d_in[24]; const float* b1 = (const float*)d_in[25];
    const float* w2 = (const float*)d_in[26]; const float* b2 = (const float*)d_in[27];
    const int* src  = (const int*)d_in[28];
    const int* dst  = (const int*)d_in[29];
    const int* gids = (const int*)d_in[30];
    float* out = (float*)d_out;

    // CSR (deterministic)
    k_zero_cnt<<<(NN+255)/256, 256>>>();
    k_hist<<<(NE+255)/256, 256>>>(dst);
    int nb = (NN+255)/256;
    k_scanA<<<nb, 256>>>();
    k_scanB<<<1, 256>>>(nb);
    k_scanC<<<nb, 256>>>();
    k_scatter<<<(NE+255)/256, 256>>>(dst);
    k_sortadj<<<(NN+255)/256, 256>>>(src);

    // embeddings + rank-1 precompute (layer-0 Cw)
    k_emb_h<<<NN/16, 280>>>(nodes_feat, emb_h_w, emb_h_b);
    k_wC<<<1, 72>>>(emb_e_w, emb_e_b, Cw, Cb);

    const int EPARTS = NE/64;            // 12500
    const int HPARTS = NN/8;             // 6250
    for(int l=0; l<4; l++){
        size_t wo = (size_t)l*HH*HH, bo = (size_t)l*HH;
        k_node2<<<(NN+31)/32, 140>>>(Aw+wo, Ab+bo, Bw+wo, Bb+bo, 0, l>0);
        k_node2<<<(NN+31)/32, 140>>>(Dw+wo, Db+bo, Ew+wo, Eb+bo, 1, 0);
        if(l == 0){
            k_edge0<<<NE/64, 144>>>(src, dst, snorm_e, edges_feat);
        } else {
            k_edge<<<NE/64, 144>>>(Cw+wo, Cb+bo, src, dst, snorm_e,
                                   edges_feat, emb_e_w, emb_e_b,
                                   (l==1) ? 1 : 2, (l<3) ? 1 : 0);
        }
        if(l < 3){
            k_red1<<<64, 160>>>(EPARTS, (EPARTS+63)/64);
            k_red2<<<1, 160>>>();
            k_bnparams<<<1, 70>>>(bn_e_g+bo, bn_e_b+bo, 1.f/(float)NE, 1);
        }
        k_agg<<<NN/8, 256>>>(snorm_n);
        k_red1<<<64, 160>>>(HPARTS, (HPARTS+63)/64);
        k_red2<<<1, 160>>>();
        k_bnparams<<<1, 70>>>(bn_h_g+bo, bn_h_b+bo, 1.f/(float)NN, 0);
    }
    k_hfinal<<<(NN*36+255)/256, 256>>>();

    k_gstart<<<1, 160>>>(gids);
    k_readout<<<NG, 256>>>(w0, b0, w1, b1, w2, b2, out);
}